// round 8
// baseline (speedup 1.0000x reference)
#include <cuda_runtime.h>
#include <cuda_bf16.h>
#include <cstdint>

#define N_NODES 50000
#define N_EDGES 800000
#define HIDDEN  128
#define H4      512
#define KC      32            // K elements per chunk
#define NCH     16            // 512 / 32
#define TILE_M  128
#define EDGE_BLOCKS (N_EDGES / TILE_M)   // 6250

#define ROWB    80                 // padded bytes per 32-half tile row
#define A_OFF_H 0
#define A_OFF_L 10240              // 128*80
#define B_OFF_H 20480
#define B_OFF_L 30720
#define STAGE   40960
#define HEAD    4096
#define SMEM_BYTES (HEAD + 2 * STAGE)   // 86016  -> 2 CTAs/SM

// Precomputed P = emb @ W1[:128] + b1, Q = emb @ W1[128:]
__device__ float g_P[(size_t)N_NODES * H4];
__device__ float g_Q[(size_t)N_NODES * H4];
__device__ int   g_idx64;
// W2^T hi/lo bf16, padded rows: [chunk(32k)][n=128][k=40 halfs]
__device__ __align__(16) unsigned short g_BH2[NCH * 128 * 40];
__device__ __align__(16) unsigned short g_BL2[NCH * 128 * 40];

typedef unsigned long long ull;
typedef unsigned int uint32;

// ---------------- helpers ----------------
__device__ __forceinline__ uint32 smem_u32(const void* p) {
    uint32 a; asm("{ .reg .u64 t; cvta.to.shared.u64 t, %1; cvt.u32.u64 %0, t; }"
                  : "=r"(a) : "l"(p)); return a;
}
__device__ __forceinline__ void ldsm4(uint32& r0, uint32& r1, uint32& r2, uint32& r3, uint32 addr) {
    asm volatile("ldmatrix.sync.aligned.m8n8.x4.shared.b16 {%0,%1,%2,%3}, [%4];"
                 : "=r"(r0), "=r"(r1), "=r"(r2), "=r"(r3) : "r"(addr));
}
__device__ __forceinline__ void mma16816(float* d, const uint32* a, uint32 b0, uint32 b1) {
    asm volatile("mma.sync.aligned.m16n8k16.row.col.f32.bf16.bf16.f32 "
                 "{%0,%1,%2,%3},{%4,%5,%6,%7},{%8,%9},{%0,%1,%2,%3};"
                 : "+f"(d[0]), "+f"(d[1]), "+f"(d[2]), "+f"(d[3])
                 : "r"(a[0]), "r"(a[1]), "r"(a[2]), "r"(a[3]), "r"(b0), "r"(b1));
}
__device__ __forceinline__ void cpasync16(uint32 dst, const void* src) {
    asm volatile("cp.async.cg.shared.global [%0], [%1], 16;" :: "r"(dst), "l"(src) : "memory");
}
#define CP_COMMIT() asm volatile("cp.async.commit_group;" ::: "memory")
#define CP_WAIT0()  asm volatile("cp.async.wait_group 0;" ::: "memory")

__device__ __forceinline__ uint32 cvt_bf16x2(float lo, float hi) {
    uint32 r; asm("cvt.rn.bf16x2.f32 %0, %1, %2;" : "=r"(r) : "f"(hi), "f"(lo)); return r;
}

// f32x2 helpers for pq_kernel
__device__ __forceinline__ ull pk2(float x, float y) {
    ull r; asm("mov.b64 %0, {%1, %2};" : "=l"(r) : "f"(x), "f"(y)); return r;
}
__device__ __forceinline__ void upk2(ull v, float& x, float& y) {
    asm("mov.b64 {%0, %1}, %2;" : "=f"(x), "=f"(y) : "l"(v));
}
__device__ __forceinline__ void fma2(ull& d, ull a, ull b) {
    asm("fma.rn.f32x2 %0, %1, %2, %0;" : "+l"(d) : "l"(a), "l"(b));
}

// ---------------------------------------------------------------------------
// Kernel 0: edge_index dtype detection (int64 vs silently-downcast int32)
// ---------------------------------------------------------------------------
__global__ void detect_kernel(const int* __restrict__ ei32)
{
    int t = threadIdx.x;
    int w = ei32[2 * t + 1];
    unsigned ballot = __ballot_sync(0xFFFFFFFFu, w != 0);
    __shared__ int any_nz;
    if (t == 0) any_nz = 0;
    __syncthreads();
    if ((t & 31) == 0 && ballot) atomicOr(&any_nz, 1);
    __syncthreads();
    if (t == 0) g_idx64 = any_nz ? 0 : 1;
}

// ---------------------------------------------------------------------------
// Kernel 0b: W2^T hi/lo bf16 split into padded [chunk][n][40] layout
// ---------------------------------------------------------------------------
__global__ void prep_w2(const float* __restrict__ W2)
{
    int i = blockIdx.x * 256 + threadIdx.x;   // 0..65535 = k*128+n
    int k = i >> 7, n = i & 127;
    float w = W2[i];
    __nv_bfloat16 hb = __float2bfloat16(w);
    float hf = __bfloat162float(hb);
    __nv_bfloat16 lb = __float2bfloat16(w - hf);
    int c = k >> 5, kl = k & 31;
    int idx = c * (128 * 40) + n * 40 + kl;
    g_BH2[idx] = __bfloat16_as_ushort(hb);
    g_BL2[idx] = __bfloat16_as_ushort(lb);
}

// ---------------------------------------------------------------------------
// Kernel 1: P/Q precompute (fp32 SIMT, f32x2) — unchanged
// ---------------------------------------------------------------------------
__global__ __launch_bounds__(256) void pq_kernel(
    const float* __restrict__ emb,
    const float* __restrict__ W1,
    const float* __restrict__ b1)
{
    __shared__ float A_s[64 * 36];
    __shared__ float B_s[32 * 128];

    const int t   = threadIdx.x;
    const int n0  = blockIdx.x * 64;
    const int j0t = blockIdx.y * 128;
    const int z   = blockIdx.z;
    float* gout = z ? g_Q : g_P;
    const float* Wbase = W1 + (size_t)z * HIDDEN * H4;

    ull acc[4][4];
#pragma unroll
    for (int i = 0; i < 4; i++)
#pragma unroll
        for (int p = 0; p < 4; p++) acc[i][p] = 0ull;

    const int e0 = (t >> 4) * 4;
    const int j0 = (t & 15) * 8;

    for (int kc = 0; kc < HIDDEN; kc += 32) {
#pragma unroll
        for (int i = 0; i < 2; i++) {
            int u  = t + i * 256;
            int nl = u >> 3;
            int k4 = (u & 7) * 4;
            int n  = n0 + nl; if (n >= N_NODES) n = N_NODES - 1;
            float4 v = *(const float4*)(emb + (size_t)n * HIDDEN + kc + k4);
            *(float4*)&A_s[nl * 36 + k4] = v;
        }
#pragma unroll
        for (int i = 0; i < 4; i++) {
            int f  = t + i * 256;
            int k  = f >> 5;
            int j4 = (f & 31) * 4;
            float4 v = *(const float4*)(Wbase + (size_t)(kc + k) * H4 + j0t + j4);
            *(float4*)&B_s[k * 128 + j4] = v;
        }
        __syncthreads();
#pragma unroll 8
        for (int kk = 0; kk < 32; kk++) {
            float4 bA = *(float4*)&B_s[kk * 128 + j0];
            float4 bB = *(float4*)&B_s[kk * 128 + j0 + 4];
            ull pb0 = pk2(bA.x, bA.y), pb1 = pk2(bA.z, bA.w);
            ull pb2 = pk2(bB.x, bB.y), pb3 = pk2(bB.z, bB.w);
#pragma unroll
            for (int i = 0; i < 4; i++) {
                float a = A_s[(e0 + i) * 36 + kk];
                ull pa = pk2(a, a);
                fma2(acc[i][0], pa, pb0);
                fma2(acc[i][1], pa, pb1);
                fma2(acc[i][2], pa, pb2);
                fma2(acc[i][3], pa, pb3);
            }
        }
        __syncthreads();
    }

#pragma unroll
    for (int i = 0; i < 4; i++) {
        int n = n0 + e0 + i;
        if (n < N_NODES) {
#pragma unroll
            for (int p = 0; p < 4; p++) {
                float x, y; upk2(acc[i][p], x, y);
                int j = j0t + j0 + p * 2;
                if (z == 0) { x += b1[j]; y += b1[j + 1]; }
                *(float2*)(&gout[(size_t)n * H4 + j]) = make_float2(x, y);
            }
        }
    }
}

// ---------------------------------------------------------------------------
// Kernel 2: warp-MMA edge kernel. M=128 x N=128 per block, 8 warps 4(M)x2(N),
// K=512 in 16 chunks of 32, 3-term bf16 split, double-buffered, 2 CTAs/SM.
// ---------------------------------------------------------------------------
__global__ __launch_bounds__(256, 2) void edge_mma_kernel(
    const void* __restrict__ ei,
    const float* __restrict__ b2,
    const float* __restrict__ W3,
    const float* __restrict__ b3,
    float* __restrict__ out)
{
    extern __shared__ char smem[];
    const uint32 sb = smem_u32(smem);
    int*   s_col = (int*)(smem);             // 512 B
    int*   s_row = (int*)(smem + 512);       // 512 B
    float* s_b2  = (float*)(smem + 1024);    // 512 B
    float* s_w3  = (float*)(smem + 1536);    // 512 B
    float* s_red = (float*)(smem + 2048);    // 1024 B

    const int t    = threadIdx.x;
    const int lane = t & 31;
    const int w    = t >> 5;
    const int wm   = w & 3;        // M block (rows wm*32)
    const int wn   = w >> 2;       // N block (cols wn*64)
    const long long eb = (long long)blockIdx.x * TILE_M;

    if (t < 128) {
        int c, r;
        if (g_idx64) {
            const long long* p = (const long long*)ei;
            c = (int)p[eb + t]; r = (int)p[(long long)N_EDGES + eb + t];
        } else {
            const int* p = (const int*)ei;
            c = p[eb + t]; r = p[N_EDGES + eb + t];
        }
        c = min(max(c, 0), N_NODES - 1);
        r = min(max(r, 0), N_NODES - 1);
        s_col[t] = c; s_row[t] = r;
    } else {
        int j = t - 128;
        s_b2[j] = b2[j]; s_w3[j] = W3[j];
    }
    __syncthreads();

    // A gather mapping: 2 threads per edge, 16 k-elems each per chunk
    const int el = t >> 1;
    const int h  = t & 1;
    const size_t colOff = (size_t)s_col[el] * H4 + (size_t)h * 16;
    const size_t rowOff = (size_t)s_row[el] * H4 + (size_t)h * 16;
    const uint32 aStore = (uint32)el * ROWB + (uint32)h * 32;

    // ldmatrix lane offsets (relative to stage base)
    const uint32 aLd0 = (uint32)(wm * 32 + (lane & 15)) * ROWB + (uint32)(lane >> 4) * 16;
    const uint32 aLd1 = aLd0 + 16 * ROWB;
    const uint32 bRow = (uint32)((lane & 7) + ((lane >> 4) << 3));
    const uint32 bLd  = ((uint32)wn * 64 + bRow) * ROWB + (uint32)((lane >> 3) & 1) * 16;

    float acc[2][8][4];
#pragma unroll
    for (int rb = 0; rb < 2; rb++)
#pragma unroll
        for (int nb = 0; nb < 8; nb++)
#pragma unroll
            for (int q = 0; q < 4; q++) acc[rb][nb][q] = 0.f;

    // ---- build A tile (relu(P+Q) hi/lo bf16) into stage stg ----
    auto buildA = [&](int chunk, int stg) {
        char* base = smem + HEAD + (size_t)stg * STAGE;
        char* AH = base + A_OFF_H;
        char* AL = base + A_OFF_L;
        const float4* pr = (const float4*)(g_P + colOff + chunk * KC);
        const float4* qr = (const float4*)(g_Q + rowOff + chunk * KC);
#pragma unroll
        for (int g = 0; g < 2; g++) {
            float4 p0 = pr[2 * g], p1 = pr[2 * g + 1];
            float4 q0 = qr[2 * g], q1 = qr[2 * g + 1];
            float a0 = fmaxf(p0.x + q0.x, 0.f), a1 = fmaxf(p0.y + q0.y, 0.f);
            float a2 = fmaxf(p0.z + q0.z, 0.f), a3 = fmaxf(p0.w + q0.w, 0.f);
            float a4 = fmaxf(p1.x + q1.x, 0.f), a5 = fmaxf(p1.y + q1.y, 0.f);
            float a6 = fmaxf(p1.z + q1.z, 0.f), a7 = fmaxf(p1.w + q1.w, 0.f);
            uint32 h01 = cvt_bf16x2(a0, a1), h23 = cvt_bf16x2(a2, a3);
            uint32 h45 = cvt_bf16x2(a4, a5), h67 = cvt_bf16x2(a6, a7);
            float f0 = __uint_as_float(h01 << 16), f1 = __uint_as_float(h01 & 0xFFFF0000u);
            float f2 = __uint_as_float(h23 << 16), f3 = __uint_as_float(h23 & 0xFFFF0000u);
            float f4 = __uint_as_float(h45 << 16), f5 = __uint_as_float(h45 & 0xFFFF0000u);
            float f6 = __uint_as_float(h67 << 16), f7 = __uint_as_float(h67 & 0xFFFF0000u);
            uint32 l01 = cvt_bf16x2(a0 - f0, a1 - f1), l23 = cvt_bf16x2(a2 - f2, a3 - f3);
            uint32 l45 = cvt_bf16x2(a4 - f4, a5 - f5), l67 = cvt_bf16x2(a6 - f6, a7 - f7);
            uint32 o = aStore + g * 16;
            *(uint4*)(AH + o) = make_uint4(h01, h23, h45, h67);
            *(uint4*)(AL + o) = make_uint4(l01, l23, l45, l67);
        }
    };
    // ---- stream B chunk (640 uint4 per hi/lo) into stage stg via cp.async ----
    auto loadB = [&](int chunk, int stg) {
        const uint4* srcH = (const uint4*)g_BH2 + chunk * 640;
        const uint4* srcL = (const uint4*)g_BL2 + chunk * 640;
        uint32 bw = sb + HEAD + (uint32)stg * STAGE;
        for (int u = t; u < 640; u += 256) {
            cpasync16(bw + B_OFF_H + u * 16, srcH + u);
            cpasync16(bw + B_OFF_L + u * 16, srcL + u);
        }
        CP_COMMIT();
    };

    // ---------------- prologue ----------------
    loadB(0, 0);
    buildA(0, 0);
    CP_WAIT0();
    __syncthreads();

    // ---------------- main loop ----------------
    for (int i = 0; i < NCH; i++) {
        const int s = i & 1;
        const uint32 bufR = sb + HEAD + (uint32)s * STAGE;

        if (i + 1 < NCH) {
            loadB(i + 1, s ^ 1);
            buildA(i + 1, s ^ 1);
        }

        // MMA phase on buffer s (rows wm*32..+31, cols wn*64..+63)
#pragma unroll
        for (int ks = 0; ks < 2; ks++) {
            const uint32 kb = (uint32)ks * 32;
            uint32 ah0[4], ah1[4], al0[4], al1[4];
            ldsm4(ah0[0], ah0[1], ah0[2], ah0[3], bufR + A_OFF_H + aLd0 + kb);
            ldsm4(ah1[0], ah1[1], ah1[2], ah1[3], bufR + A_OFF_H + aLd1 + kb);
            ldsm4(al0[0], al0[1], al0[2], al0[3], bufR + A_OFF_L + aLd0 + kb);
            ldsm4(al1[0], al1[1], al1[2], al1[3], bufR + A_OFF_L + aLd1 + kb);
#pragma unroll
            for (int p = 0; p < 4; p++) {
                uint32 r0, r1, r2, r3;
                ldsm4(r0, r1, r2, r3, bufR + B_OFF_H + bLd + (uint32)p * (16 * ROWB) + kb);
                mma16816(acc[0][2 * p],     ah0, r0, r1);
                mma16816(acc[0][2 * p + 1], ah0, r2, r3);
                mma16816(acc[1][2 * p],     ah1, r0, r1);
                mma16816(acc[1][2 * p + 1], ah1, r2, r3);
                mma16816(acc[0][2 * p],     al0, r0, r1);
                mma16816(acc[0][2 * p + 1], al0, r2, r3);
                mma16816(acc[1][2 * p],     al1, r0, r1);
                mma16816(acc[1][2 * p + 1], al1, r2, r3);
                ldsm4(r0, r1, r2, r3, bufR + B_OFF_L + bLd + (uint32)p * (16 * ROWB) + kb);
                mma16816(acc[0][2 * p],     ah0, r0, r1);
                mma16816(acc[0][2 * p + 1], ah0, r2, r3);
                mma16816(acc[1][2 * p],     ah1, r0, r1);
                mma16816(acc[1][2 * p + 1], ah1, r2, r3);
            }
        }
        CP_WAIT0();
        __syncthreads();
    }

    // ---------------- epilogue: fold layer 3, cross-warp N reduce ----------------
    const int g4 = lane >> 2;
    const int t4 = lane & 3;
#pragma unroll
    for (int rb = 0; rb < 2; rb++) {
        float sA = 0.f, sB = 0.f;
#pragma unroll
        for (int nb = 0; nb < 8; nb++) {
            int c0 = wn * 64 + nb * 8 + 2 * t4;
            int c1 = c0 + 1;
            sA += fmaxf(acc[rb][nb][0] + s_b2[c0], 0.f) * s_w3[c0];
            sA += fmaxf(acc[rb][nb][1] + s_b2[c1], 0.f) * s_w3[c1];
            sB += fmaxf(acc[rb][nb][2] + s_b2[c0], 0.f) * s_w3[c0];
            sB += fmaxf(acc[rb][nb][3] + s_b2[c1], 0.f) * s_w3[c1];
        }
        sA += __shfl_xor_sync(0xFFFFFFFFu, sA, 1);
        sA += __shfl_xor_sync(0xFFFFFFFFu, sA, 2);
        sB += __shfl_xor_sync(0xFFFFFFFFu, sB, 1);
        sB += __shfl_xor_sync(0xFFFFFFFFu, sB, 2);
        if (t4 == 0) {
            int row = wm * 32 + rb * 16 + g4;
            s_red[wn * 128 + row]     = sA;
            s_red[wn * 128 + row + 8] = sB;
        }
    }
    __syncthreads();
    if (t < 128) {
        out[eb + t] = s_red[t] + s_red[128 + t] + b3[0];
    }
}

extern "C" void kernel_launch(void* const* d_in, const int* in_sizes, int n_in,
                              void* d_out, int out_size)
{
    const float* emb = (const float*)d_in[0];
    const void*  ei  = d_in[1];
    const float* W1  = (const float*)d_in[2];
    const float* b1  = (const float*)d_in[3];
    const float* W2  = (const float*)d_in[4];
    const float* b2  = (const float*)d_in[5];
    const float* W3  = (const float*)d_in[6];
    const float* b3  = (const float*)d_in[7];
    float* out = (float*)d_out;
    (void)in_sizes; (void)n_in; (void)out_size;

    cudaFuncSetAttribute(edge_mma_kernel,
                         cudaFuncAttributeMaxDynamicSharedMemorySize, SMEM_BYTES);

    detect_kernel<<<1, 128>>>((const int*)ei);
    prep_w2<<<256, 256>>>(W2);
    dim3 g1((N_NODES + 63) / 64, H4 / 128, 2);
    pq_kernel<<<g1, 256>>>(emb, W1, b1);
    edge_mma_kernel<<<EDGE_BLOCKS, 256, SMEM_BYTES>>>(ei, b2, W3, b3, out);
}

// round 9
// speedup vs baseline: 1.6209x; 1.6209x over previous
#include <cuda_runtime.h>
#include <cuda_bf16.h>
#include <cstdint>

#define N_NODES 50000
#define N_EDGES 800000
#define HIDDEN  128
#define H4      512
#define KC      32            // K elements per chunk
#define NCH     16            // 512 / 32
#define TILE_M  128
#define EDGE_BLOCKS (N_EDGES / TILE_M)   // 6250

#define ROWB    80                 // padded bytes per 32-half tile row
#define A_OFF_H 0
#define A_OFF_L 10240              // 128*80
#define B_OFF   20480              // B hi (10240) then lo (10240), contiguous
#define B_BYTES 20480
#define STAGE   40960
#define HEAD    4096
#define MBAR_OFF 3072
#define SMEM_BYTES (HEAD + 2 * STAGE)   // 86016  -> 2 CTAs/SM

// Precomputed P = emb @ W1[:128] + b1, Q = emb @ W1[128:]
__device__ float g_P[(size_t)N_NODES * H4];
__device__ float g_Q[(size_t)N_NODES * H4];
__device__ int   g_idx64;
// W2^T packed: [chunk][hi 128x40 | lo 128x40] halfs, contiguous 20480B per chunk
__device__ __align__(128) unsigned short g_B2[NCH * 2 * 128 * 40];

typedef unsigned long long ull;
typedef unsigned int uint32;

// ---------------- helpers ----------------
__device__ __forceinline__ uint32 smem_u32(const void* p) {
    uint32 a; asm("{ .reg .u64 t; cvta.to.shared.u64 t, %1; cvt.u32.u64 %0, t; }"
                  : "=r"(a) : "l"(p)); return a;
}
__device__ __forceinline__ void ldsm4(uint32& r0, uint32& r1, uint32& r2, uint32& r3, uint32 addr) {
    asm volatile("ldmatrix.sync.aligned.m8n8.x4.shared.b16 {%0,%1,%2,%3}, [%4];"
                 : "=r"(r0), "=r"(r1), "=r"(r2), "=r"(r3) : "r"(addr));
}
__device__ __forceinline__ void mma16816(float* d, const uint32* a, uint32 b0, uint32 b1) {
    asm volatile("mma.sync.aligned.m16n8k16.row.col.f32.bf16.bf16.f32 "
                 "{%0,%1,%2,%3},{%4,%5,%6,%7},{%8,%9},{%0,%1,%2,%3};"
                 : "+f"(d[0]), "+f"(d[1]), "+f"(d[2]), "+f"(d[3])
                 : "r"(a[0]), "r"(a[1]), "r"(a[2]), "r"(a[3]), "r"(b0), "r"(b1));
}
#define MBAR_INIT(m, c)  asm volatile("mbarrier.init.shared.b64 [%0], %1;" :: "r"(m), "r"(c) : "memory")
#define MBAR_EXPECT(m, b) asm volatile("mbarrier.arrive.expect_tx.shared.b64 _, [%0], %1;" :: "r"(m), "r"(b) : "memory")
#define BULK_G2S(dst, src, sz, m) \
    asm volatile("cp.async.bulk.shared::cluster.global.mbarrier::complete_tx::bytes [%0], [%1], %2, [%3];" \
                 :: "r"(dst), "l"(src), "r"(sz), "r"(m) : "memory")

__device__ __forceinline__ void mbar_wait(uint32 m, uint32 parity) {
    uint32 done;
    asm volatile("{ .reg .pred p; mbarrier.try_wait.parity.shared.b64 p, [%1], %2; selp.b32 %0, 1, 0, p; }"
                 : "=r"(done) : "r"(m), "r"(parity) : "memory");
    if (!done) {
        asm volatile("{ .reg .pred P1;\n\t"
                     "W_%=:\n\t"
                     "mbarrier.try_wait.parity.shared.b64 P1, [%0], %1;\n\t"
                     "@P1 bra.uni D_%=;\n\t"
                     "bra.uni W_%=;\n\t"
                     "D_%=:\n\t}" :: "r"(m), "r"(parity) : "memory");
    }
}

__device__ __forceinline__ uint32 cvt_bf16x2(float lo, float hi) {
    uint32 r; asm("cvt.rn.bf16x2.f32 %0, %1, %2;" : "=r"(r) : "f"(hi), "f"(lo)); return r;
}

// f32x2 helpers for pq_kernel
__device__ __forceinline__ ull pk2(float x, float y) {
    ull r; asm("mov.b64 %0, {%1, %2};" : "=l"(r) : "f"(x), "f"(y)); return r;
}
__device__ __forceinline__ void upk2(ull v, float& x, float& y) {
    asm("mov.b64 {%0, %1}, %2;" : "=f"(x), "=f"(y) : "l"(v));
}
__device__ __forceinline__ void fma2(ull& d, ull a, ull b) {
    asm("fma.rn.f32x2 %0, %1, %2, %0;" : "+l"(d) : "l"(a), "l"(b));
}

// ---------------------------------------------------------------------------
// Kernel 0: edge_index dtype detection (int64 vs silently-downcast int32)
// ---------------------------------------------------------------------------
__global__ void detect_kernel(const int* __restrict__ ei32)
{
    int t = threadIdx.x;
    int w = ei32[2 * t + 1];
    unsigned ballot = __ballot_sync(0xFFFFFFFFu, w != 0);
    __shared__ int any_nz;
    if (t == 0) any_nz = 0;
    __syncthreads();
    if ((t & 31) == 0 && ballot) atomicOr(&any_nz, 1);
    __syncthreads();
    if (t == 0) g_idx64 = any_nz ? 0 : 1;
}

// ---------------------------------------------------------------------------
// Kernel 0b: W2^T hi/lo bf16 split into packed [chunk][hi|lo][n][40] layout
// ---------------------------------------------------------------------------
__global__ void prep_w2(const float* __restrict__ W2)
{
    int i = blockIdx.x * 256 + threadIdx.x;   // 0..65535 = k*128+n
    int k = i >> 7, n = i & 127;
    float w = W2[i];
    __nv_bfloat16 hb = __float2bfloat16(w);
    float hf = __bfloat162float(hb);
    __nv_bfloat16 lb = __float2bfloat16(w - hf);
    int c = k >> 5, kl = k & 31;
    int base = c * (2 * 128 * 40) + n * 40 + kl;
    g_B2[base]            = __bfloat16_as_ushort(hb);
    g_B2[base + 128 * 40] = __bfloat16_as_ushort(lb);
}

// ---------------------------------------------------------------------------
// Kernel 1: P/Q precompute (fp32 SIMT, f32x2) — unchanged
// ---------------------------------------------------------------------------
__global__ __launch_bounds__(256) void pq_kernel(
    const float* __restrict__ emb,
    const float* __restrict__ W1,
    const float* __restrict__ b1)
{
    __shared__ float A_s[64 * 36];
    __shared__ float B_s[32 * 128];

    const int t   = threadIdx.x;
    const int n0  = blockIdx.x * 64;
    const int j0t = blockIdx.y * 128;
    const int z   = blockIdx.z;
    float* gout = z ? g_Q : g_P;
    const float* Wbase = W1 + (size_t)z * HIDDEN * H4;

    ull acc[4][4];
#pragma unroll
    for (int i = 0; i < 4; i++)
#pragma unroll
        for (int p = 0; p < 4; p++) acc[i][p] = 0ull;

    const int e0 = (t >> 4) * 4;
    const int j0 = (t & 15) * 8;

    for (int kc = 0; kc < HIDDEN; kc += 32) {
#pragma unroll
        for (int i = 0; i < 2; i++) {
            int u  = t + i * 256;
            int nl = u >> 3;
            int k4 = (u & 7) * 4;
            int n  = n0 + nl; if (n >= N_NODES) n = N_NODES - 1;
            float4 v = *(const float4*)(emb + (size_t)n * HIDDEN + kc + k4);
            *(float4*)&A_s[nl * 36 + k4] = v;
        }
#pragma unroll
        for (int i = 0; i < 4; i++) {
            int f  = t + i * 256;
            int k  = f >> 5;
            int j4 = (f & 31) * 4;
            float4 v = *(const float4*)(Wbase + (size_t)(kc + k) * H4 + j0t + j4);
            *(float4*)&B_s[k * 128 + j4] = v;
        }
        __syncthreads();
#pragma unroll 8
        for (int kk = 0; kk < 32; kk++) {
            float4 bA = *(float4*)&B_s[kk * 128 + j0];
            float4 bB = *(float4*)&B_s[kk * 128 + j0 + 4];
            ull pb0 = pk2(bA.x, bA.y), pb1 = pk2(bA.z, bA.w);
            ull pb2 = pk2(bB.x, bB.y), pb3 = pk2(bB.z, bB.w);
#pragma unroll
            for (int i = 0; i < 4; i++) {
                float a = A_s[(e0 + i) * 36 + kk];
                ull pa = pk2(a, a);
                fma2(acc[i][0], pa, pb0);
                fma2(acc[i][1], pa, pb1);
                fma2(acc[i][2], pa, pb2);
                fma2(acc[i][3], pa, pb3);
            }
        }
        __syncthreads();
    }

#pragma unroll
    for (int i = 0; i < 4; i++) {
        int n = n0 + e0 + i;
        if (n < N_NODES) {
#pragma unroll
            for (int p = 0; p < 4; p++) {
                float x, y; upk2(acc[i][p], x, y);
                int j = j0t + j0 + p * 2;
                if (z == 0) { x += b1[j]; y += b1[j + 1]; }
                *(float2*)(&gout[(size_t)n * H4 + j]) = make_float2(x, y);
            }
        }
    }
}

// ---------------------------------------------------------------------------
// Kernel 2: warp-MMA edge kernel. M=128 x N=128 per block, 8 warps 4(M)x2(N),
// K=512 in 16 chunks of 32, 3-term bf16 split, double-buffered, 2 CTAs/SM.
// B chunks arrive via one cp.async.bulk (20KB) per chunk + mbarrier.
// ---------------------------------------------------------------------------
__global__ __launch_bounds__(256, 2) void edge_mma_kernel(
    const void* __restrict__ ei,
    const float* __restrict__ b2,
    const float* __restrict__ W3,
    const float* __restrict__ b3,
    float* __restrict__ out)
{
    extern __shared__ char smem[];
    const uint32 sb = smem_u32(smem);
    int*   s_col = (int*)(smem);             // 512 B
    int*   s_row = (int*)(smem + 512);       // 512 B
    float* s_b2  = (float*)(smem + 1024);    // 512 B
    float* s_w3  = (float*)(smem + 1536);    // 512 B
    float* s_red = (float*)(smem + 2048);    // 1024 B
    // mbarriers at MBAR_OFF + 16*s

    const int t    = threadIdx.x;
    const int lane = t & 31;
    const int w    = t >> 5;
    const int wm   = w & 3;        // M block (rows wm*32)
    const int wn   = w >> 2;       // N block (cols wn*64)
    const long long eb = (long long)blockIdx.x * TILE_M;

    if (t < 128) {
        int c, r;
        if (g_idx64) {
            const long long* p = (const long long*)ei;
            c = (int)p[eb + t]; r = (int)p[(long long)N_EDGES + eb + t];
        } else {
            const int* p = (const int*)ei;
            c = p[eb + t]; r = p[N_EDGES + eb + t];
        }
        c = min(max(c, 0), N_NODES - 1);
        r = min(max(r, 0), N_NODES - 1);
        s_col[t] = c; s_row[t] = r;
    } else {
        int j = t - 128;
        s_b2[j] = b2[j]; s_w3[j] = W3[j];
    }
    if (t == 0) {
        MBAR_INIT(sb + MBAR_OFF, 1);
        MBAR_INIT(sb + MBAR_OFF + 16, 1);
    }
    __syncthreads();

    // A gather mapping: 2 threads per edge, 16 k-elems each per chunk
    const int el = t >> 1;
    const int h  = t & 1;
    const size_t colOff = (size_t)s_col[el] * H4 + (size_t)h * 16;
    const size_t rowOff = (size_t)s_row[el] * H4 + (size_t)h * 16;
    const uint32 aStore = (uint32)el * ROWB + (uint32)h * 32;

    // ldmatrix lane offsets (relative to stage base)
    const uint32 aLd0 = (uint32)(wm * 32 + (lane & 15)) * ROWB + (uint32)(lane >> 4) * 16;
    const uint32 aLd1 = aLd0 + 16 * ROWB;
    const uint32 bRow = (uint32)((lane & 7) + ((lane >> 4) << 3));
    const uint32 bLd  = ((uint32)wn * 64 + bRow) * ROWB + (uint32)((lane >> 3) & 1) * 16;

    float acc[2][8][4];
#pragma unroll
    for (int rb = 0; rb < 2; rb++)
#pragma unroll
        for (int nb = 0; nb < 8; nb++)
#pragma unroll
            for (int q = 0; q < 4; q++) acc[rb][nb][q] = 0.f;

    // ---- build A tile (relu(P+Q) hi/lo bf16) into stage stg ----
    auto buildA = [&](int chunk, int stg) {
        char* base = smem + HEAD + (size_t)stg * STAGE;
        char* AH = base + A_OFF_H;
        char* AL = base + A_OFF_L;
        const float4* pr = (const float4*)(g_P + colOff + chunk * KC);
        const float4* qr = (const float4*)(g_Q + rowOff + chunk * KC);
#pragma unroll
        for (int g = 0; g < 2; g++) {
            float4 p0 = pr[2 * g], p1 = pr[2 * g + 1];
            float4 q0 = qr[2 * g], q1 = qr[2 * g + 1];
            float a0 = fmaxf(p0.x + q0.x, 0.f), a1 = fmaxf(p0.y + q0.y, 0.f);
            float a2 = fmaxf(p0.z + q0.z, 0.f), a3 = fmaxf(p0.w + q0.w, 0.f);
            float a4 = fmaxf(p1.x + q1.x, 0.f), a5 = fmaxf(p1.y + q1.y, 0.f);
            float a6 = fmaxf(p1.z + q1.z, 0.f), a7 = fmaxf(p1.w + q1.w, 0.f);
            uint32 h01 = cvt_bf16x2(a0, a1), h23 = cvt_bf16x2(a2, a3);
            uint32 h45 = cvt_bf16x2(a4, a5), h67 = cvt_bf16x2(a6, a7);
            float f0 = __uint_as_float(h01 << 16), f1 = __uint_as_float(h01 & 0xFFFF0000u);
            float f2 = __uint_as_float(h23 << 16), f3 = __uint_as_float(h23 & 0xFFFF0000u);
            float f4 = __uint_as_float(h45 << 16), f5 = __uint_as_float(h45 & 0xFFFF0000u);
            float f6 = __uint_as_float(h67 << 16), f7 = __uint_as_float(h67 & 0xFFFF0000u);
            uint32 l01 = cvt_bf16x2(a0 - f0, a1 - f1), l23 = cvt_bf16x2(a2 - f2, a3 - f3);
            uint32 l45 = cvt_bf16x2(a4 - f4, a5 - f5), l67 = cvt_bf16x2(a6 - f6, a7 - f7);
            uint32 o = aStore + g * 16;
            *(uint4*)(AH + o) = make_uint4(h01, h23, h45, h67);
            *(uint4*)(AL + o) = make_uint4(l01, l23, l45, l67);
        }
    };
    // ---- one bulk copy per chunk: 20KB (hi+lo) into stage stg ----
    auto loadB = [&](int chunk, int stg) {
        if (t == 0) {
            uint32 m = sb + MBAR_OFF + (uint32)stg * 16;
            MBAR_EXPECT(m, B_BYTES);
            const char* src = (const char*)g_B2 + (size_t)chunk * B_BYTES;
            BULK_G2S(sb + HEAD + (uint32)stg * STAGE + B_OFF, src, B_BYTES, m);
        }
    };

    // ---------------- prologue ----------------
    loadB(0, 0);
    buildA(0, 0);
    __syncthreads();

    // ---------------- main loop ----------------
    for (int i = 0; i < NCH; i++) {
        const int s = i & 1;
        const uint32 bufR = sb + HEAD + (uint32)s * STAGE;

        // B for chunk i ready?
        mbar_wait(sb + MBAR_OFF + (uint32)s * 16, (uint32)((i >> 1) & 1));

        if (i + 1 < NCH) {
            loadB(i + 1, s ^ 1);
            buildA(i + 1, s ^ 1);
        }

        // MMA phase on buffer s (rows wm*32..+31, cols wn*64..+63)
#pragma unroll
        for (int ks = 0; ks < 2; ks++) {
            const uint32 kb = (uint32)ks * 32;
            uint32 ah0[4], ah1[4], al0[4], al1[4];
            ldsm4(ah0[0], ah0[1], ah0[2], ah0[3], bufR + A_OFF_H + aLd0 + kb);
            ldsm4(ah1[0], ah1[1], ah1[2], ah1[3], bufR + A_OFF_H + aLd1 + kb);
            ldsm4(al0[0], al0[1], al0[2], al0[3], bufR + A_OFF_L + aLd0 + kb);
            ldsm4(al1[0], al1[1], al1[2], al1[3], bufR + A_OFF_L + aLd1 + kb);
#pragma unroll
            for (int p = 0; p < 4; p++) {
                uint32 r0, r1, r2, r3;
                // B hi at B_OFF, B lo at B_OFF + 10240
                ldsm4(r0, r1, r2, r3, bufR + B_OFF + bLd + (uint32)p * (16 * ROWB) + kb);
                mma16816(acc[0][2 * p],     ah0, r0, r1);
                mma16816(acc[0][2 * p + 1], ah0, r2, r3);
                mma16816(acc[1][2 * p],     ah1, r0, r1);
                mma16816(acc[1][2 * p + 1], ah1, r2, r3);
                mma16816(acc[0][2 * p],     al0, r0, r1);
                mma16816(acc[0][2 * p + 1], al0, r2, r3);
                mma16816(acc[1][2 * p],     al1, r0, r1);
                mma16816(acc[1][2 * p + 1], al1, r2, r3);
                ldsm4(r0, r1, r2, r3, bufR + B_OFF + 10240 + bLd + (uint32)p * (16 * ROWB) + kb);
                mma16816(acc[0][2 * p],     ah0, r0, r1);
                mma16816(acc[0][2 * p + 1], ah0, r2, r3);
                mma16816(acc[1][2 * p],     ah1, r0, r1);
                mma16816(acc[1][2 * p + 1], ah1, r2, r3);
            }
        }
        __syncthreads();
    }

    // ---------------- epilogue: fold layer 3, cross-warp N reduce ----------------
    const int g4 = lane >> 2;
    const int t4 = lane & 3;
#pragma unroll
    for (int rb = 0; rb < 2; rb++) {
        float sA = 0.f, sB = 0.f;
#pragma unroll
        for (int nb = 0; nb < 8; nb++) {
            int c0 = wn * 64 + nb * 8 + 2 * t4;
            int c1 = c0 + 1;
            sA += fmaxf(acc[rb][nb][0] + s_b2[c0], 0.f) * s_w3[c0];
            sA += fmaxf(acc[rb][nb][1] + s_b2[c1], 0.f) * s_w3[c1];
            sB += fmaxf(acc[rb][nb][2] + s_b2[c0], 0.f) * s_w3[c0];
            sB += fmaxf(acc[rb][nb][3] + s_b2[c1], 0.f) * s_w3[c1];
        }
        sA += __shfl_xor_sync(0xFFFFFFFFu, sA, 1);
        sA += __shfl_xor_sync(0xFFFFFFFFu, sA, 2);
        sB += __shfl_xor_sync(0xFFFFFFFFu, sB, 1);
        sB += __shfl_xor_sync(0xFFFFFFFFu, sB, 2);
        if (t4 == 0) {
            int row = wm * 32 + rb * 16 + g4;
            s_red[wn * 128 + row]     = sA;
            s_red[wn * 128 + row + 8] = sB;
        }
    }
    __syncthreads();
    if (t < 128) {
        out[eb + t] = s_red[t] + s_red[128 + t] + b3[0];
    }
}

extern "C" void kernel_launch(void* const* d_in, const int* in_sizes, int n_in,
                              void* d_out, int out_size)
{
    const float* emb = (const float*)d_in[0];
    const void*  ei  = d_in[1];
    const float* W1  = (const float*)d_in[2];
    const float* b1  = (const float*)d_in[3];
    const float* W2  = (const float*)d_in[4];
    const float* b2  = (const float*)d_in[5];
    const float* W3  = (const float*)d_in[6];
    const float* b3  = (const float*)d_in[7];
    float* out = (float*)d_out;
    (void)in_sizes; (void)n_in; (void)out_size;

    cudaFuncSetAttribute(edge_mma_kernel,
                         cudaFuncAttributeMaxDynamicSharedMemorySize, SMEM_BYTES);

    detect_kernel<<<1, 128>>>((const int*)ei);
    prep_w2<<<256, 256>>>(W2);
    dim3 g1((N_NODES + 63) / 64, H4 / 128, 2);
    pq_kernel<<<g1, 256>>>(emb, W1, b1);
    edge_mma_kernel<<<EDGE_BLOCKS, 256, SMEM_BYTES>>>(ei, b2, W3, b3, out);
}

// round 10
// speedup vs baseline: 2.0925x; 1.2910x over previous
#include <cuda_runtime.h>
#include <cuda_bf16.h>
#include <cstdint>

#define N_NODES 50000
#define N_EDGES 800000
#define HIDDEN  128
#define H4      512
#define KC      32
#define NCH     16            // edge: 512/32
#define NCH_PQ  4             // pq:   128/32
#define TILE_M  128
#define EDGE_BLOCKS (N_EDGES / TILE_M)
#define NB_M    ((N_NODES + 127) / 128)   // 391

#define ROWB    80
#define A_OFF_H 0
#define A_OFF_L 10240
#define B_OFF   20480
#define B_BYTES 20480
#define STAGE   40960
#define HEAD    4096
#define MBAR_OFF 3072
#define SMEM_BYTES (HEAD + 2 * STAGE)   // 86016 -> 2 CTAs/SM

__device__ float g_P[(size_t)N_NODES * H4];
__device__ float g_Q[(size_t)N_NODES * H4];
__device__ int   g_idx64;
// W2^T packed: [chunk][hi 128x40 | lo 128x40]
__device__ __align__(128) unsigned short g_B2[NCH * 2 * 128 * 40];
// W1 packed: [z][ntile][chunk][hi 128x40 | lo 128x40]
__device__ __align__(128) unsigned short g_B1[2 * 4 * NCH_PQ * 2 * 128 * 40];

typedef unsigned long long ull;
typedef unsigned int uint32;

__device__ __forceinline__ uint32 smem_u32(const void* p) {
    uint32 a; asm("{ .reg .u64 t; cvta.to.shared.u64 t, %1; cvt.u32.u64 %0, t; }"
                  : "=r"(a) : "l"(p)); return a;
}
__device__ __forceinline__ void ldsm4(uint32& r0, uint32& r1, uint32& r2, uint32& r3, uint32 addr) {
    asm volatile("ldmatrix.sync.aligned.m8n8.x4.shared.b16 {%0,%1,%2,%3}, [%4];"
                 : "=r"(r0), "=r"(r1), "=r"(r2), "=r"(r3) : "r"(addr));
}
__device__ __forceinline__ void mma16816(float* d, const uint32* a, uint32 b0, uint32 b1) {
    asm volatile("mma.sync.aligned.m16n8k16.row.col.f32.bf16.bf16.f32 "
                 "{%0,%1,%2,%3},{%4,%5,%6,%7},{%8,%9},{%0,%1,%2,%3};"
                 : "+f"(d[0]), "+f"(d[1]), "+f"(d[2]), "+f"(d[3])
                 : "r"(a[0]), "r"(a[1]), "r"(a[2]), "r"(a[3]), "r"(b0), "r"(b1));
}
#define MBAR_INIT(m, c)  asm volatile("mbarrier.init.shared.b64 [%0], %1;" :: "r"(m), "r"(c) : "memory")
#define MBAR_EXPECT(m, b) asm volatile("mbarrier.arrive.expect_tx.shared.b64 _, [%0], %1;" :: "r"(m), "r"(b) : "memory")
#define BULK_G2S(dst, src, sz, m) \
    asm volatile("cp.async.bulk.shared::cluster.global.mbarrier::complete_tx::bytes [%0], [%1], %2, [%3];" \
                 :: "r"(dst), "l"(src), "r"(sz), "r"(m) : "memory")

__device__ __forceinline__ void mbar_wait(uint32 m, uint32 parity) {
    uint32 done;
    asm volatile("{ .reg .pred p; mbarrier.try_wait.parity.shared.b64 p, [%1], %2; selp.b32 %0, 1, 0, p; }"
                 : "=r"(done) : "r"(m), "r"(parity) : "memory");
    if (!done) {
        asm volatile("{ .reg .pred P1;\n\t"
                     "W_%=:\n\t"
                     "mbarrier.try_wait.parity.shared.b64 P1, [%0], %1;\n\t"
                     "@P1 bra.uni D_%=;\n\t"
                     "bra.uni W_%=;\n\t"
                     "D_%=:\n\t}" :: "r"(m), "r"(parity) : "memory");
    }
}
__device__ __forceinline__ uint32 cvt_bf16x2(float lo, float hi) {
    uint32 r; asm("cvt.rn.bf16x2.f32 %0, %1, %2;" : "=r"(r) : "f"(hi), "f"(lo)); return r;
}

// ---------------------------------------------------------------------------
// Kernel 0: edge_index dtype detection
// ---------------------------------------------------------------------------
__global__ void detect_kernel(const int* __restrict__ ei32)
{
    int t = threadIdx.x;
    int w = ei32[2 * t + 1];
    unsigned ballot = __ballot_sync(0xFFFFFFFFu, w != 0);
    __shared__ int any_nz;
    if (t == 0) any_nz = 0;
    __syncthreads();
    if ((t & 31) == 0 && ballot) atomicOr(&any_nz, 1);
    __syncthreads();
    if (t == 0) g_idx64 = any_nz ? 0 : 1;
}

// ---------------------------------------------------------------------------
// Kernel 0b: W2^T hi/lo split into packed [chunk][hi|lo][n][40]
// ---------------------------------------------------------------------------
__global__ void prep_w2(const float* __restrict__ W2)
{
    int i = blockIdx.x * 256 + threadIdx.x;   // k*128+n
    int k = i >> 7, n = i & 127;
    float w = W2[i];
    __nv_bfloat16 hb = __float2bfloat16(w);
    float hf = __bfloat162float(hb);
    __nv_bfloat16 lb = __float2bfloat16(w - hf);
    int c = k >> 5, kl = k & 31;
    int base = c * (2 * 128 * 40) + n * 40 + kl;
    g_B2[base]            = __bfloat16_as_ushort(hb);
    g_B2[base + 128 * 40] = __bfloat16_as_ushort(lb);
}

// ---------------------------------------------------------------------------
// Kernel 0c: W1 hi/lo split into packed [z][nt][chunk][hi|lo][n][40]
// W1 is [256, 512] row-major (rows = input dim, cols = output dim)
// ---------------------------------------------------------------------------
__global__ void prep_w1(const float* __restrict__ W1)
{
    int i = blockIdx.x * 256 + threadIdx.x;   // 0..131071
    int r  = i >> 9;          // input row 0..255
    int cg = i & 511;         // output col
    int z  = r >> 7, k = r & 127;
    int nt = cg >> 7, n = cg & 127;
    float w = W1[(size_t)r * H4 + cg];
    __nv_bfloat16 hb = __float2bfloat16(w);
    float hf = __bfloat162float(hb);
    __nv_bfloat16 lb = __float2bfloat16(w - hf);
    int c = k >> 5, kl = k & 31;
    int base = (((z * 4 + nt) * NCH_PQ + c)) * (2 * 128 * 40) + n * 40 + kl;
    g_B1[base]            = __bfloat16_as_ushort(hb);
    g_B1[base + 128 * 40] = __bfloat16_as_ushort(lb);
}

// ---------------------------------------------------------------------------
// Kernel 1: P/Q via HMMA. M=128 nodes x N=128 outs per CTA, K=128 (4 chunks),
// 3-term bf16 split, double-buffered, 2 CTAs/SM.
// grid: (391, 4 ntiles, 2 z)
// ---------------------------------------------------------------------------
__global__ __launch_bounds__(256, 2) void pq_mma_kernel(
    const float* __restrict__ emb,
    const float* __restrict__ b1)
{
    extern __shared__ char smem[];
    const uint32 sb = smem_u32(smem);
    float* s_b1 = (float*)(smem);            // 512 B

    const int t    = threadIdx.x;
    const int lane = t & 31;
    const int w    = t >> 5;
    const int wm   = w & 3;
    const int wn   = w >> 2;
    const int mt   = blockIdx.x;
    const int nt   = blockIdx.y;
    const int z    = blockIdx.z;
    const int n0   = mt * 128;

    if (t < 128) s_b1[t] = (z == 0) ? b1[nt * 128 + t] : 0.f;
    if (t == 0) {
        MBAR_INIT(sb + MBAR_OFF, 1);
        MBAR_INIT(sb + MBAR_OFF + 16, 1);
    }
    __syncthreads();

    // A build mapping: 2 threads per node row
    const int el = t >> 1;
    const int h  = t & 1;
    int nodeR = n0 + el; if (nodeR >= N_NODES) nodeR = N_NODES - 1;
    const size_t embOff = (size_t)nodeR * HIDDEN + (size_t)h * 16;
    const uint32 aStore = (uint32)el * ROWB + (uint32)h * 32;

    const uint32 aLd0 = (uint32)(wm * 32 + (lane & 15)) * ROWB + (uint32)(lane >> 4) * 16;
    const uint32 aLd1 = aLd0 + 16 * ROWB;
    const uint32 bRow = (uint32)((lane & 7) + ((lane >> 4) << 3));
    const uint32 bLd  = ((uint32)wn * 64 + bRow) * ROWB + (uint32)((lane >> 3) & 1) * 16;

    float acc[2][8][4];
#pragma unroll
    for (int rb = 0; rb < 2; rb++)
#pragma unroll
        for (int nb = 0; nb < 8; nb++)
#pragma unroll
            for (int q = 0; q < 4; q++) acc[rb][nb][q] = 0.f;

    auto buildA = [&](int chunk, int stg) {
        char* base = smem + HEAD + (size_t)stg * STAGE;
        char* AH = base + A_OFF_H;
        char* AL = base + A_OFF_L;
        const float4* pr = (const float4*)(emb + embOff + chunk * KC);
#pragma unroll
        for (int g = 0; g < 2; g++) {
            float4 p0 = pr[2 * g], p1 = pr[2 * g + 1];
            uint32 h01 = cvt_bf16x2(p0.x, p0.y), h23 = cvt_bf16x2(p0.z, p0.w);
            uint32 h45 = cvt_bf16x2(p1.x, p1.y), h67 = cvt_bf16x2(p1.z, p1.w);
            float f0 = __uint_as_float(h01 << 16), f1 = __uint_as_float(h01 & 0xFFFF0000u);
            float f2 = __uint_as_float(h23 << 16), f3 = __uint_as_float(h23 & 0xFFFF0000u);
            float f4 = __uint_as_float(h45 << 16), f5 = __uint_as_float(h45 & 0xFFFF0000u);
            float f6 = __uint_as_float(h67 << 16), f7 = __uint_as_float(h67 & 0xFFFF0000u);
            uint32 l01 = cvt_bf16x2(p0.x - f0, p0.y - f1), l23 = cvt_bf16x2(p0.z - f2, p0.w - f3);
            uint32 l45 = cvt_bf16x2(p1.x - f4, p1.y - f5), l67 = cvt_bf16x2(p1.z - f6, p1.w - f7);
            uint32 o = aStore + g * 16;
            *(uint4*)(AH + o) = make_uint4(h01, h23, h45, h67);
            *(uint4*)(AL + o) = make_uint4(l01, l23, l45, l67);
        }
    };
    auto loadB = [&](int chunk, int stg) {
        if (t == 0) {
            uint32 m = sb + MBAR_OFF + (uint32)stg * 16;
            MBAR_EXPECT(m, B_BYTES);
            const char* src = (const char*)g_B1 +
                ((size_t)((z * 4 + nt) * NCH_PQ + chunk)) * B_BYTES;
            BULK_G2S(sb + HEAD + (uint32)stg * STAGE + B_OFF, src, B_BYTES, m);
        }
    };

    loadB(0, 0);
    buildA(0, 0);
    __syncthreads();

    for (int i = 0; i < NCH_PQ; i++) {
        const int s = i & 1;
        const uint32 bufR = sb + HEAD + (uint32)s * STAGE;

        if (i + 1 < NCH_PQ) loadB(i + 1, s ^ 1);
        mbar_wait(sb + MBAR_OFF + (uint32)s * 16, (uint32)((i >> 1) & 1));
        if (i + 1 < NCH_PQ) buildA(i + 1, s ^ 1);

#pragma unroll
        for (int ks = 0; ks < 2; ks++) {
            const uint32 kb = (uint32)ks * 32;
            uint32 ah0[4], ah1[4], al0[4], al1[4];
            ldsm4(ah0[0], ah0[1], ah0[2], ah0[3], bufR + A_OFF_H + aLd0 + kb);
            ldsm4(ah1[0], ah1[1], ah1[2], ah1[3], bufR + A_OFF_H + aLd1 + kb);
            ldsm4(al0[0], al0[1], al0[2], al0[3], bufR + A_OFF_L + aLd0 + kb);
            ldsm4(al1[0], al1[1], al1[2], al1[3], bufR + A_OFF_L + aLd1 + kb);
#pragma unroll
            for (int p = 0; p < 4; p++) {
                uint32 r0, r1, r2, r3;
                ldsm4(r0, r1, r2, r3, bufR + B_OFF + bLd + (uint32)p * (16 * ROWB) + kb);
                mma16816(acc[0][2 * p],     ah0, r0, r1);
                mma16816(acc[0][2 * p + 1], ah0, r2, r3);
                mma16816(acc[1][2 * p],     ah1, r0, r1);
                mma16816(acc[1][2 * p + 1], ah1, r2, r3);
                mma16816(acc[0][2 * p],     al0, r0, r1);
                mma16816(acc[0][2 * p + 1], al0, r2, r3);
                mma16816(acc[1][2 * p],     al1, r0, r1);
                mma16816(acc[1][2 * p + 1], al1, r2, r3);
                ldsm4(r0, r1, r2, r3, bufR + B_OFF + 10240 + bLd + (uint32)p * (16 * ROWB) + kb);
                mma16816(acc[0][2 * p],     ah0, r0, r1);
                mma16816(acc[0][2 * p + 1], ah0, r2, r3);
                mma16816(acc[1][2 * p],     ah1, r0, r1);
                mma16816(acc[1][2 * p + 1], ah1, r2, r3);
            }
        }
        __syncthreads();
    }

    // epilogue: write P/Q rows (fp32), +b1 for z=0
    float* gout = z ? g_Q : g_P;
    const int g4 = lane >> 2;
    const int t4 = lane & 3;
#pragma unroll
    for (int rb = 0; rb < 2; rb++) {
#pragma unroll
        for (int nb = 0; nb < 8; nb++) {
            int cl = wn * 64 + nb * 8 + 2 * t4;           // local col
            int cgl = nt * 128 + cl;                       // global col
            float bb0 = s_b1[cl], bb1 = s_b1[cl + 1];
            int r0 = n0 + wm * 32 + rb * 16 + g4;
            int r1 = r0 + 8;
            if (r0 < N_NODES)
                *(float2*)(&gout[(size_t)r0 * H4 + cgl]) =
                    make_float2(acc[rb][nb][0] + bb0, acc[rb][nb][1] + bb1);
            if (r1 < N_NODES)
                *(float2*)(&gout[(size_t)r1 * H4 + cgl]) =
                    make_float2(acc[rb][nb][2] + bb0, acc[rb][nb][3] + bb1);
        }
    }
}

// ---------------------------------------------------------------------------
// Kernel 2: warp-MMA edge kernel (unchanged config; loadB hoisted above wait)
// ---------------------------------------------------------------------------
__global__ __launch_bounds__(256, 2) void edge_mma_kernel(
    const void* __restrict__ ei,
    const float* __restrict__ b2,
    const float* __restrict__ W3,
    const float* __restrict__ b3,
    float* __restrict__ out)
{
    extern __shared__ char smem[];
    const uint32 sb = smem_u32(smem);
    int*   s_col = (int*)(smem);
    int*   s_row = (int*)(smem + 512);
    float* s_b2  = (float*)(smem + 1024);
    float* s_w3  = (float*)(smem + 1536);
    float* s_red = (float*)(smem + 2048);

    const int t    = threadIdx.x;
    const int lane = t & 31;
    const int w    = t >> 5;
    const int wm   = w & 3;
    const int wn   = w >> 2;
    const long long eb = (long long)blockIdx.x * TILE_M;

    if (t < 128) {
        int c, r;
        if (g_idx64) {
            const long long* p = (const long long*)ei;
            c = (int)p[eb + t]; r = (int)p[(long long)N_EDGES + eb + t];
        } else {
            const int* p = (const int*)ei;
            c = p[eb + t]; r = p[N_EDGES + eb + t];
        }
        c = min(max(c, 0), N_NODES - 1);
        r = min(max(r, 0), N_NODES - 1);
        s_col[t] = c; s_row[t] = r;
    } else {
        int j = t - 128;
        s_b2[j] = b2[j]; s_w3[j] = W3[j];
    }
    if (t == 0) {
        MBAR_INIT(sb + MBAR_OFF, 1);
        MBAR_INIT(sb + MBAR_OFF + 16, 1);
    }
    __syncthreads();

    const int el = t >> 1;
    const int h  = t & 1;
    const size_t colOff = (size_t)s_col[el] * H4 + (size_t)h * 16;
    const size_t rowOff = (size_t)s_row[el] * H4 + (size_t)h * 16;
    const uint32 aStore = (uint32)el * ROWB + (uint32)h * 32;

    const uint32 aLd0 = (uint32)(wm * 32 + (lane & 15)) * ROWB + (uint32)(lane >> 4) * 16;
    const uint32 aLd1 = aLd0 + 16 * ROWB;
    const uint32 bRow = (uint32)((lane & 7) + ((lane >> 4) << 3));
    const uint32 bLd  = ((uint32)wn * 64 + bRow) * ROWB + (uint32)((lane >> 3) & 1) * 16;

    float acc[2][8][4];
#pragma unroll
    for (int rb = 0; rb < 2; rb++)
#pragma unroll
        for (int nb = 0; nb < 8; nb++)
#pragma unroll
            for (int q = 0; q < 4; q++) acc[rb][nb][q] = 0.f;

    auto buildA = [&](int chunk, int stg) {
        char* base = smem + HEAD + (size_t)stg * STAGE;
        char* AH = base + A_OFF_H;
        char* AL = base + A_OFF_L;
        const float4* pr = (const float4*)(g_P + colOff + chunk * KC);
        const float4* qr = (const float4*)(g_Q + rowOff + chunk * KC);
#pragma unroll
        for (int g = 0; g < 2; g++) {
            float4 p0 = pr[2 * g], p1 = pr[2 * g + 1];
            float4 q0 = qr[2 * g], q1 = qr[2 * g + 1];
            float a0 = fmaxf(p0.x + q0.x, 0.f), a1 = fmaxf(p0.y + q0.y, 0.f);
            float a2 = fmaxf(p0.z + q0.z, 0.f), a3 = fmaxf(p0.w + q0.w, 0.f);
            float a4 = fmaxf(p1.x + q1.x, 0.f), a5 = fmaxf(p1.y + q1.y, 0.f);
            float a6 = fmaxf(p1.z + q1.z, 0.f), a7 = fmaxf(p1.w + q1.w, 0.f);
            uint32 h01 = cvt_bf16x2(a0, a1), h23 = cvt_bf16x2(a2, a3);
            uint32 h45 = cvt_bf16x2(a4, a5), h67 = cvt_bf16x2(a6, a7);
            float f0 = __uint_as_float(h01 << 16), f1 = __uint_as_float(h01 & 0xFFFF0000u);
            float f2 = __uint_as_float(h23 << 16), f3 = __uint_as_float(h23 & 0xFFFF0000u);
            float f4 = __uint_as_float(h45 << 16), f5 = __uint_as_float(h45 & 0xFFFF0000u);
            float f6 = __uint_as_float(h67 << 16), f7 = __uint_as_float(h67 & 0xFFFF0000u);
            uint32 l01 = cvt_bf16x2(a0 - f0, a1 - f1), l23 = cvt_bf16x2(a2 - f2, a3 - f3);
            uint32 l45 = cvt_bf16x2(a4 - f4, a5 - f5), l67 = cvt_bf16x2(a6 - f6, a7 - f7);
            uint32 o = aStore + g * 16;
            *(uint4*)(AH + o) = make_uint4(h01, h23, h45, h67);
            *(uint4*)(AL + o) = make_uint4(l01, l23, l45, l67);
        }
    };
    auto loadB = [&](int chunk, int stg) {
        if (t == 0) {
            uint32 m = sb + MBAR_OFF + (uint32)stg * 16;
            MBAR_EXPECT(m, B_BYTES);
            const char* src = (const char*)g_B2 + (size_t)chunk * B_BYTES;
            BULK_G2S(sb + HEAD + (uint32)stg * STAGE + B_OFF, src, B_BYTES, m);
        }
    };

    loadB(0, 0);
    buildA(0, 0);
    __syncthreads();

    for (int i = 0; i < NCH; i++) {
        const int s = i & 1;
        const uint32 bufR = sb + HEAD + (uint32)s * STAGE;

        // hoist next bulk copy ahead of this chunk's wait (stage s^1 is free)
        if (i + 1 < NCH) loadB(i + 1, s ^ 1);
        mbar_wait(sb + MBAR_OFF + (uint32)s * 16, (uint32)((i >> 1) & 1));
        if (i + 1 < NCH) buildA(i + 1, s ^ 1);

#pragma unroll
        for (int ks = 0; ks < 2; ks++) {
            const uint32 kb = (uint32)ks * 32;
            uint32 ah0[4], ah1[4], al0[4], al1[4];
            ldsm4(ah0[0], ah0[1], ah0[2], ah0[3], bufR + A_OFF_H + aLd0 + kb);
            ldsm4(ah1[0], ah1[1], ah1[2], ah1[3], bufR + A_OFF_H + aLd1 + kb);
            ldsm4(al0[0], al0[1], al0[2], al0[3], bufR + A_OFF_L + aLd0 + kb);
            ldsm4(al1[0], al1[1], al1[2], al1[3], bufR + A_OFF_L + aLd1 + kb);
#pragma unroll
            for (int p = 0; p < 4; p++) {
                uint32 r0, r1, r2, r3;
                ldsm4(r0, r1, r2, r3, bufR + B_OFF + bLd + (uint32)p * (16 * ROWB) + kb);
                mma16816(acc[0][2 * p],     ah0, r0, r1);
                mma16816(acc[0][2 * p + 1], ah0, r2, r3);
                mma16816(acc[1][2 * p],     ah1, r0, r1);
                mma16816(acc[1][2 * p + 1], ah1, r2, r3);
                mma16816(acc[0][2 * p],     al0, r0, r1);
                mma16816(acc[0][2 * p + 1], al0, r2, r3);
                mma16816(acc[1][2 * p],     al1, r0, r1);
                mma16816(acc[1][2 * p + 1], al1, r2, r3);
                ldsm4(r0, r1, r2, r3, bufR + B_OFF + 10240 + bLd + (uint32)p * (16 * ROWB) + kb);
                mma16816(acc[0][2 * p],     ah0, r0, r1);
                mma16816(acc[0][2 * p + 1], ah0, r2, r3);
                mma16816(acc[1][2 * p],     ah1, r0, r1);
                mma16816(acc[1][2 * p + 1], ah1, r2, r3);
            }
        }
        __syncthreads();
    }

    const int g4 = lane >> 2;
    const int t4 = lane & 3;
#pragma unroll
    for (int rb = 0; rb < 2; rb++) {
        float sA = 0.f, sB = 0.f;
#pragma unroll
        for (int nb = 0; nb < 8; nb++) {
            int c0 = wn * 64 + nb * 8 + 2 * t4;
            int c1 = c0 + 1;
            sA += fmaxf(acc[rb][nb][0] + s_b2[c0], 0.f) * s_w3[c0];
            sA += fmaxf(acc[rb][nb][1] + s_b2[c1], 0.f) * s_w3[c1];
            sB += fmaxf(acc[rb][nb][2] + s_b2[c0], 0.f) * s_w3[c0];
            sB += fmaxf(acc[rb][nb][3] + s_b2[c1], 0.f) * s_w3[c1];
        }
        sA += __shfl_xor_sync(0xFFFFFFFFu, sA, 1);
        sA += __shfl_xor_sync(0xFFFFFFFFu, sA, 2);
        sB += __shfl_xor_sync(0xFFFFFFFFu, sB, 1);
        sB += __shfl_xor_sync(0xFFFFFFFFu, sB, 2);
        if (t4 == 0) {
            int row = wm * 32 + rb * 16 + g4;
            s_red[wn * 128 + row]     = sA;
            s_red[wn * 128 + row + 8] = sB;
        }
    }
    __syncthreads();
    if (t < 128) {
        out[eb + t] = s_red[t] + s_red[128 + t] + b3[0];
    }
}

extern "C" void kernel_launch(void* const* d_in, const int* in_sizes, int n_in,
                              void* d_out, int out_size)
{
    const float* emb = (const float*)d_in[0];
    const void*  ei  = d_in[1];
    const float* W1  = (const float*)d_in[2];
    const float* b1  = (const float*)d_in[3];
    const float* W2  = (const float*)d_in[4];
    const float* b2  = (const float*)d_in[5];
    const float* W3  = (const float*)d_in[6];
    const float* b3  = (const float*)d_in[7];
    float* out = (float*)d_out;
    (void)in_sizes; (void)n_in; (void)out_size;

    cudaFuncSetAttribute(edge_mma_kernel,
                         cudaFuncAttributeMaxDynamicSharedMemorySize, SMEM_BYTES);
    cudaFuncSetAttribute(pq_mma_kernel,
                         cudaFuncAttributeMaxDynamicSharedMemorySize, SMEM_BYTES);

    detect_kernel<<<1, 128>>>((const int*)ei);
    prep_w2<<<256, 256>>>(W2);
    prep_w1<<<512, 256>>>(W1);
    dim3 gpq(NB_M, 4, 2);
    pq_mma_kernel<<<gpq, 256, SMEM_BYTES>>>(emb, b1);
    edge_mma_kernel<<<EDGE_BLOCKS, 256, SMEM_BYTES>>>(ei, b2, W3, b3, out);
}